// round 2
// baseline (speedup 1.0000x reference)
#include <cuda_runtime.h>
#include <cstdint>

#define Sdim 2048
#define Bdim 32
#define Hdim 512
#define Gdim 2048   // 4*H
#define NCTA_REC 128
#define THR_REC 256

typedef unsigned long long ull;

// Scratch (module-load allocated)
__device__ float g_xg [(size_t)Sdim * Bdim * Gdim];   // [s][b][4H]
__device__ float g_h1s[(size_t)Sdim * Bdim * Hdim];   // layer-1 hidden seq [s][b][H]
__device__ float g_hbuf[2][Bdim * Hdim];              // ping-pong h(t)
__device__ int   g_flags[NCTA_REC];
__device__ unsigned g_cnt;
__device__ unsigned g_gen;

// packed f32x2 FMA: acc = a*b + acc (elementwise on both 32-bit halves)
#define FMA2(acc, x, y) \
    asm("fma.rn.f32x2 %0, %1, %2, %0;" : "+l"(acc) : "l"(x), "l"(y))
#define UNPACK2(lo, hi, v) \
    asm("mov.b64 {%0,%1}, %2;" : "=f"(lo), "=f"(hi) : "l"(v))

// ---------------- init grid barrier (sense-reversal, replay-safe) ----------------
__device__ __forceinline__ void grid_barrier() {
    __syncthreads();
    if (threadIdx.x == 0) {
        __threadfence();
        unsigned gen = *(volatile unsigned*)&g_gen;
        unsigned old = atomicAdd(&g_cnt, 1u);
        if (old == gridDim.x - 1) {
            atomicExch(&g_cnt, 0u);
            __threadfence();
            atomicAdd(&g_gen, 1u);
        } else {
            while (*(volatile unsigned*)&g_gen == gen) { __nanosleep(32); }
        }
        __threadfence();
    }
    __syncthreads();
}

// ---------------- input projection GEMM (f32x2, 128x128x16 tiles) ----------------
// C[row][g] = sum_k A[row][k]*W[g][k] + bih[g] + bhh[g],  row=(s*B+b)
__global__ __launch_bounds__(256, 1) void gemm_xg_kernel(
    const float* __restrict__ X, const float* __restrict__ W,
    const float* __restrict__ bih, const float* __restrict__ bhh, int layer0)
{
    // smem tiles: [row 0..127][kp 0..7] k-pair (8B) units, swizzled:
    //   phys = row*8 + (kp ^ ((row>>3)&7))
    __shared__ ull As[128 * 8];
    __shared__ ull Bs[128 * 8];

    int tid  = threadIdx.x;
    int row0 = blockIdx.y * 128;
    int col0 = blockIdx.x * 128;

    // load assignment: 512 16B-chunks per operand; thread owns chunks {tid, tid+256}
    int rA0 = tid >> 2,          c40 = tid & 3;
    int rA1 = (tid + 256) >> 2,  c41 = (tid + 256) & 3;

    const float* aP0;
    const float* aP1;
    if (layer0) {
        int b0_ = rA0 & 31, s0_ = (row0 + rA0) >> 5;
        int b1_ = rA1 & 31, s1_ = (row0 + rA1) >> 5;
        aP0 = X + ((size_t)b0_ * Sdim + s0_) * Hdim;
        aP1 = X + ((size_t)b1_ * Sdim + s1_) * Hdim;
    } else {
        aP0 = g_h1s + (size_t)(row0 + rA0) * Hdim;
        aP1 = g_h1s + (size_t)(row0 + rA1) * Hdim;
    }
    const float* bP0 = W + (size_t)(col0 + rA0) * Hdim;
    const float* bP1 = W + (size_t)(col0 + rA1) * Hdim;

    int tx = tid & 15, ty = tid >> 4;
    int i0 = ty * 8, j0 = tx * 8;
    int sA = ty & 7, sB = tx & 7;

    ull acc[8][8];
#pragma unroll
    for (int i = 0; i < 8; i++)
#pragma unroll
        for (int j = 0; j < 8; j++) acc[i][j] = 0ull;

    float4 pa0, pa1, pb0, pb1;
    // prefetch tile 0
    pa0 = __ldg((const float4*)(aP0 + c40 * 4));
    pa1 = __ldg((const float4*)(aP1 + c41 * 4));
    pb0 = __ldg((const float4*)(bP0 + c40 * 4));
    pb1 = __ldg((const float4*)(bP1 + c41 * 4));
    {
        int s0 = (rA0 >> 3) & 7, s1 = (rA1 >> 3) & 7;
        *(float2*)&As[rA0 * 8 + ((2*c40)   ^ s0)] = make_float2(pa0.x, pa0.y);
        *(float2*)&As[rA0 * 8 + ((2*c40+1) ^ s0)] = make_float2(pa0.z, pa0.w);
        *(float2*)&As[rA1 * 8 + ((2*c41)   ^ s1)] = make_float2(pa1.x, pa1.y);
        *(float2*)&As[rA1 * 8 + ((2*c41+1) ^ s1)] = make_float2(pa1.z, pa1.w);
        *(float2*)&Bs[rA0 * 8 + ((2*c40)   ^ s0)] = make_float2(pb0.x, pb0.y);
        *(float2*)&Bs[rA0 * 8 + ((2*c40+1) ^ s0)] = make_float2(pb0.z, pb0.w);
        *(float2*)&Bs[rA1 * 8 + ((2*c41)   ^ s1)] = make_float2(pb1.x, pb1.y);
        *(float2*)&Bs[rA1 * 8 + ((2*c41+1) ^ s1)] = make_float2(pb1.z, pb1.w);
    }
    __syncthreads();

    for (int kt = 0; kt < 32; kt++) {
        if (kt < 31) {
            int k0 = (kt + 1) * 16;
            pa0 = __ldg((const float4*)(aP0 + k0 + c40 * 4));
            pa1 = __ldg((const float4*)(aP1 + k0 + c41 * 4));
            pb0 = __ldg((const float4*)(bP0 + k0 + c40 * 4));
            pb1 = __ldg((const float4*)(bP1 + k0 + c41 * 4));
        }
#pragma unroll
        for (int kp = 0; kp < 8; kp++) {
            ull a2[8], b2[8];
#pragma unroll
            for (int i = 0; i < 8; i++) a2[i] = As[(i0 + i) * 8 + (kp ^ sA)];
#pragma unroll
            for (int j = 0; j < 8; j++) b2[j] = Bs[(j0 + j) * 8 + (kp ^ sB)];
#pragma unroll
            for (int i = 0; i < 8; i++)
#pragma unroll
                for (int j = 0; j < 8; j++) FMA2(acc[i][j], a2[i], b2[j]);
        }
        __syncthreads();
        if (kt < 31) {
            int s0 = (rA0 >> 3) & 7, s1 = (rA1 >> 3) & 7;
            *(float2*)&As[rA0 * 8 + ((2*c40)   ^ s0)] = make_float2(pa0.x, pa0.y);
            *(float2*)&As[rA0 * 8 + ((2*c40+1) ^ s0)] = make_float2(pa0.z, pa0.w);
            *(float2*)&As[rA1 * 8 + ((2*c41)   ^ s1)] = make_float2(pa1.x, pa1.y);
            *(float2*)&As[rA1 * 8 + ((2*c41+1) ^ s1)] = make_float2(pa1.z, pa1.w);
            *(float2*)&Bs[rA0 * 8 + ((2*c40)   ^ s0)] = make_float2(pb0.x, pb0.y);
            *(float2*)&Bs[rA0 * 8 + ((2*c40+1) ^ s0)] = make_float2(pb0.z, pb0.w);
            *(float2*)&Bs[rA1 * 8 + ((2*c41)   ^ s1)] = make_float2(pb1.x, pb1.y);
            *(float2*)&Bs[rA1 * 8 + ((2*c41+1) ^ s1)] = make_float2(pb1.z, pb1.w);
            __syncthreads();
        }
    }

    // bias + horizontal reduce + store
    float4 bi0 = __ldg((const float4*)(bih + col0 + j0));
    float4 bi1 = __ldg((const float4*)(bih + col0 + j0 + 4));
    float4 bh0 = __ldg((const float4*)(bhh + col0 + j0));
    float4 bh1 = __ldg((const float4*)(bhh + col0 + j0 + 4));
    float bias[8] = {bi0.x+bh0.x, bi0.y+bh0.y, bi0.z+bh0.z, bi0.w+bh0.w,
                     bi1.x+bh1.x, bi1.y+bh1.y, bi1.z+bh1.z, bi1.w+bh1.w};
#pragma unroll
    for (int i = 0; i < 8; i++) {
        float o[8];
#pragma unroll
        for (int j = 0; j < 8; j++) {
            float lo, hi;
            UNPACK2(lo, hi, acc[i][j]);
            o[j] = lo + hi + bias[j];
        }
        float* crow = g_xg + (size_t)(row0 + i0 + i) * Gdim + col0 + j0;
        *(float4*)(crow)     = make_float4(o[0], o[1], o[2], o[3]);
        *(float4*)(crow + 4) = make_float4(o[4], o[5], o[6], o[7]);
    }
}

// ---------------- persistent recurrence (f32x2, conflict-free, flag barrier) ----------------
// 128 CTAs x 256 threads. CTA owns hidden j0..j0+3.
// Thread: gh = tid>>7 (gate pair: 0->{i,f}, 1->{g,o}); within 128: warp w2, lane l;
//         b = w2*8 + (l&7), jj = l>>3.
__global__ __launch_bounds__(THR_REC, 1) void lstm_recur_kernel(
    const float* __restrict__ Whh, float* __restrict__ hseq,
    int out_bsh, float* __restrict__ hTo, float* __restrict__ cTo)
{
    extern __shared__ float sm[];
    float* Wsm  = sm;                       // [16][520], row r = q*4+jj
    float* hsm  = Wsm + 16 * 520;           // [32][516]
    float* exg  = hsm + 32 * 516;           // [128] g-gate dots
    float* exo  = exg + 128;                // [128] o-gate dots

    int tid = threadIdx.x;
    int gh  = tid >> 7;
    int l7  = tid & 127;
    int b   = ((l7 >> 5) << 3) + (l7 & 7);
    int jj  = (l7 & 31) >> 3;
    int j0  = blockIdx.x * 4;
    int q0  = gh * 2, q1 = gh * 2 + 1;

    // stage Whh rows (reused all steps): 16 rows x 512 floats
    for (int idx = tid; idx < 16 * 128; idx += THR_REC) {
        int r = idx >> 7, kq = (idx & 127) * 4;
        int q = r >> 2, j = r & 3;
        float4 v = *(const float4*)(Whh + (size_t)(q * Hdim + j0 + j) * Hdim + kq);
        *(float4*)&Wsm[r * 520 + kq] = v;
    }
    // reset flags + h(0)=0
    if (tid == 0) g_flags[blockIdx.x] = 0;
    if (gh == 0) g_hbuf[0][b * Hdim + j0 + jj] = 0.0f;
    float c = 0.0f;
    grid_barrier();   // all resets visible before anyone writes flag=1

    const float* xg_t = g_xg + (size_t)b * Gdim + (j0 + jj);
    const ulonglong2* wa = (const ulonglong2*)&Wsm[(q0 * 4 + jj) * 520];
    const ulonglong2* wb = (const ulonglong2*)&Wsm[(q1 * 4 + jj) * 520];
    const ulonglong2* hh = (const ulonglong2*)&hsm[b * 516];

    for (int t = 0; t < Sdim; t++) {
        int cur = t & 1;
        float x0 = __ldg(xg_t + (size_t)q0 * Hdim);
        float x1 = __ldg(xg_t + (size_t)q1 * Hdim);

        // wait for h(t-1): all CTAs completed >= t steps
        if (tid < NCTA_REC) {
            while (__ldcg(&g_flags[tid]) < t) { __nanosleep(64); }
        }
        __threadfence();   // acquire
        __syncthreads();

        // stage h(t-1): 64KB global -> smem [b][516]
        const float4* src = (const float4*)g_hbuf[cur];
#pragma unroll
        for (int i = 0; i < 16; i++) {
            int idx = tid + i * THR_REC;
            float4 v = __ldcg(src + idx);
            int bb = idx >> 7, kq4 = idx & 127;
            *(float4*)&hsm[bb * 516 + kq4 * 4] = v;
        }
        __syncthreads();

        ull a0 = 0ull, a1 = 0ull, d0 = 0ull, d1 = 0ull;
#pragma unroll 4
        for (int kq = 0; kq < 128; kq++) {
            ulonglong2 hv = hh[kq];
            ulonglong2 w0 = wa[kq];
            ulonglong2 w1 = wb[kq];
            FMA2(a0, w0.x, hv.x); FMA2(a1, w0.y, hv.y);
            FMA2(d0, w1.x, hv.x); FMA2(d1, w1.y, hv.y);
        }
        float p0, p1, p2, p3;
        UNPACK2(p0, p1, a0); UNPACK2(p2, p3, a1);
        float dot0 = (p0 + p2) + (p1 + p3) + x0;
        UNPACK2(p0, p1, d0); UNPACK2(p2, p3, d1);
        float dot1 = (p0 + p2) + (p1 + p3) + x1;

        if (gh == 1) {   // g, o dots
            exg[jj * 32 + b] = dot0;
            exo[jj * 32 + b] = dot1;
        }
        __syncthreads();

        if (gh == 0) {   // i, f dots; combine and update state
            float dg = exg[jj * 32 + b];
            float do_ = exo[jj * 32 + b];
            float ig = 1.0f / (1.0f + __expf(-dot0));
            float fg = 1.0f / (1.0f + __expf(-dot1));
            float gg = tanhf(dg);
            float og = 1.0f / (1.0f + __expf(-do_));
            c = fg * c + ig * gg;
            float h = og * tanhf(c);

            g_hbuf[cur ^ 1][b * Hdim + j0 + jj] = h;
            if (out_bsh) {
                hseq[((size_t)b * Sdim + t) * Hdim + j0 + jj] = h;
            } else {
                g_h1s[((size_t)t * Bdim + b) * Hdim + j0 + jj] = h;
            }
            if (hTo && t == Sdim - 1) {
                hTo[b * Hdim + j0 + jj] = h;
                cTo[b * Hdim + j0 + jj] = c;
            }
            __threadfence();
        }
        __syncthreads();
        if (tid == 0) *(volatile int*)&g_flags[blockIdx.x] = t + 1;

        xg_t += (size_t)Bdim * Gdim;
    }
}

// ---------------- launch ----------------
extern "C" void kernel_launch(void* const* d_in, const int* in_sizes, int n_in,
                              void* d_out, int out_size) {
    (void)in_sizes; (void)n_in;
    const float* X   = (const float*)d_in[0];
    const float* Wih = (const float*)d_in[1];
    const float* Whh = (const float*)d_in[2];
    const float* bih = (const float*)d_in[3];
    const float* bhh = (const float*)d_in[4];
    float* out = (float*)d_out;

    size_t ht_elems = (size_t)Bdim * Sdim * Hdim;
    float* hTo = nullptr; float* cTo = nullptr;
    if ((size_t)out_size >= ht_elems + 2 * (size_t)Bdim * Hdim) {
        hTo = out + ht_elems;
        cTo = hTo + (size_t)Bdim * Hdim;
    }

    const int smem_rec = (16 * 520 + 32 * 516 + 256) * 4;   // 100352 B
    cudaFuncSetAttribute(lstm_recur_kernel,
                         cudaFuncAttributeMaxDynamicSharedMemorySize, smem_rec);

    dim3 ggrid(Gdim / 128, (Sdim * Bdim) / 128);  // (16, 512)

    // Layer 0
    gemm_xg_kernel<<<ggrid, 256>>>(X, Wih, bih, bhh, 1);
    lstm_recur_kernel<<<NCTA_REC, THR_REC, smem_rec>>>(Whh, nullptr, 0, nullptr, nullptr);
    // Layer 1
    gemm_xg_kernel<<<ggrid, 256>>>(X, Wih + (size_t)Gdim * Hdim,
                                   bih + Gdim, bhh + Gdim, 0);
    lstm_recur_kernel<<<NCTA_REC, THR_REC, smem_rec>>>(Whh + (size_t)Gdim * Hdim,
                                                       out, 1, hTo, cTo);
}

// round 4
// speedup vs baseline: 1.2487x; 1.2487x over previous
#include <cuda_runtime.h>
#include <cuda_bf16.h>
#include <cstdint>

#define Sdim 2048
#define Bdim 32
#define Hdim 512
#define Gdim 2048   // 4*H
#define NCTA_REC 128
#define THR_REC 128

typedef unsigned long long ull;

// ---------------- scratch (module-load allocated) ----------------
__device__ float g_xg [(size_t)Sdim * Bdim * Gdim];               // [s*B+b][4H]
__device__ __nv_bfloat16 g_Ahi [(size_t)Sdim * Bdim * Hdim];      // X split  [s*B+b][k]
__device__ __nv_bfloat16 g_Alo [(size_t)Sdim * Bdim * Hdim];
__device__ __nv_bfloat16 g_h1hi[(size_t)Sdim * Bdim * Hdim];      // h1 split [t*B+b][k]
__device__ __nv_bfloat16 g_h1lo[(size_t)Sdim * Bdim * Hdim];
__device__ __nv_bfloat16 g_Whi [2 * (size_t)Gdim * Hdim];
__device__ __nv_bfloat16 g_Wlo [2 * (size_t)Gdim * Hdim];
__device__ float g_hbuf[2][Bdim * Hdim];
__device__ unsigned g_cnt;
__device__ unsigned g_gen;

// ---------------- PTX helpers ----------------
__device__ __forceinline__ uint32_t smem_u32(const void* p) {
    uint32_t a;
    asm("{ .reg .u64 t; cvta.to.shared.u64 t, %1; cvt.u32.u64 %0, t; }" : "=r"(a) : "l"(p));
    return a;
}
#define CP_ASYNC16(dst, src) \
    asm volatile("cp.async.cg.shared.global [%0], [%1], 16;" :: "r"(dst), "l"(src))
#define CP_COMMIT() asm volatile("cp.async.commit_group;" ::: "memory")
#define CP_WAIT1()  asm volatile("cp.async.wait_group 1;" ::: "memory")
#define CP_WAIT0()  asm volatile("cp.async.wait_group 0;" ::: "memory")

__device__ __forceinline__ void ldm_x4(uint32_t* r, uint32_t addr) {
    asm volatile("ldmatrix.sync.aligned.m8n8.x4.shared.b16 {%0,%1,%2,%3}, [%4];"
                 : "=r"(r[0]), "=r"(r[1]), "=r"(r[2]), "=r"(r[3]) : "r"(addr));
}
__device__ __forceinline__ void mma_bf16(float* d, const uint32_t* a, const uint32_t* b) {
    asm volatile(
        "mma.sync.aligned.m16n8k16.row.col.f32.bf16.bf16.f32 "
        "{%0,%1,%2,%3}, {%4,%5,%6,%7}, {%8,%9}, {%0,%1,%2,%3};"
        : "+f"(d[0]), "+f"(d[1]), "+f"(d[2]), "+f"(d[3])
        : "r"(a[0]), "r"(a[1]), "r"(a[2]), "r"(a[3]), "r"(b[0]), "r"(b[1]));
}

// ---------------- grid barrier (replay-safe) ----------------
__device__ __forceinline__ void grid_barrier() {
    __syncthreads();
    if (threadIdx.x == 0) {
        __threadfence();
        unsigned gen = *(volatile unsigned*)&g_gen;
        unsigned old = atomicAdd(&g_cnt, 1u);
        if (old == gridDim.x - 1) {
            atomicExch(&g_cnt, 0u);
            __threadfence();
            atomicAdd(&g_gen, 1u);
        } else {
            while (*(volatile unsigned*)&g_gen == gen) { __nanosleep(32); }
        }
        __threadfence();
    }
    __syncthreads();
}

// ---------------- fp32 -> bf16 hi/lo split ----------------
__device__ __forceinline__ void split4(float4 v, ull& hi, ull& lo) {
    union { __nv_bfloat16 h[4]; ull u; } H, L;
    float f[4] = {v.x, v.y, v.z, v.w};
#pragma unroll
    for (int i = 0; i < 4; i++) {
        __nv_bfloat16 a = __float2bfloat16_rn(f[i]);
        H.h[i] = a;
        L.h[i] = __float2bfloat16_rn(f[i] - __bfloat162float(a));
    }
    hi = H.u; lo = L.u;
}

// X[b][s][k] -> g_Ahi/g_Alo[(s*B+b)][k]
__global__ __launch_bounds__(256) void conv_x_kernel(const float* __restrict__ X) {
    size_t i = (size_t)blockIdx.x * 256 + threadIdx.x;   // float4 index
    int row = (int)(i >> 7);
    int c4  = (int)(i & 127);
    int b = row & 31, s = row >> 5;
    float4 v = __ldg((const float4*)(X + ((size_t)b * Sdim + s) * Hdim + c4 * 4));
    ull hi, lo;
    split4(v, hi, lo);
    *(ull*)(g_Ahi + (size_t)row * Hdim + c4 * 4) = hi;
    *(ull*)(g_Alo + (size_t)row * Hdim + c4 * 4) = lo;
}

// Wih[2][4H][H] -> g_Whi/g_Wlo
__global__ __launch_bounds__(256) void conv_w_kernel(const float* __restrict__ W) {
    size_t i = (size_t)blockIdx.x * 256 + threadIdx.x;   // 524288 float4's
    float4 v = __ldg((const float4*)W + i);
    ull hi, lo;
    split4(v, hi, lo);
    *(ull*)(g_Whi + i * 4) = hi;
    *(ull*)(g_Wlo + i * 4) = lo;
}

// ---------------- mma.sync split-bf16 GEMM ----------------
// C[row][g] = sum_k A[row][k]*W[g][k] + bih[g] + bhh[g]
// block tile 128x128, K chunks of 32, double-buffered cp.async.
// 8 warps: wm = wid&1 (64 rows), wn = wid>>1 (32 cols).
#define TSTRIDE 80                 // bytes per smem row (32 bf16 + pad)
#define MAT_B   (128 * TSTRIDE)    // 10240
#define STAGE_B (4 * MAT_B)        // 40960

__global__ __launch_bounds__(256, 1) void gemm_mma_kernel(
    int src_h1, int layer,
    const float* __restrict__ bih, const float* __restrict__ bhh)
{
    extern __shared__ char smem[];
    uint32_t sb = smem_u32(smem);
    int tid = threadIdx.x, wid = tid >> 5, lane = tid & 31;
    int col0 = blockIdx.x * 128;
    int row0 = blockIdx.y * 128;
    int wm = wid & 1, wn = wid >> 1;

    const __nv_bfloat16* a0p = (src_h1 ? g_h1hi : g_Ahi) + (size_t)row0 * Hdim;
    const __nv_bfloat16* a1p = (src_h1 ? g_h1lo : g_Alo) + (size_t)row0 * Hdim;
    const __nv_bfloat16* w0p = g_Whi + (size_t)layer * Gdim * Hdim + (size_t)col0 * Hdim;
    const __nv_bfloat16* w1p = g_Wlo + (size_t)layer * Gdim * Hdim + (size_t)col0 * Hdim;

    int ldr  = tid >> 2;          // 0..63  (row within first 64)
    int ldkc = tid & 3;           // 16B chunk within 64B

#define PREFETCH(stg, k0)                                                         \
    do {                                                                          \
        _Pragma("unroll")                                                         \
        for (int m = 0; m < 4; m++) {                                             \
            const __nv_bfloat16* mp = (m == 0 ? a0p : m == 1 ? a1p :              \
                                       m == 2 ? w0p : w1p);                       \
            _Pragma("unroll")                                                     \
            for (int i = 0; i < 2; i++) {                                         \
                int r = ldr + i * 64;                                             \
                uint32_t dst = sb + (stg) * STAGE_B + m * MAT_B +                 \
                               r * TSTRIDE + ldkc * 16;                           \
                const void* srcp = mp + (size_t)r * Hdim + (k0) + ldkc * 8;       \
                CP_ASYNC16(dst, srcp);                                            \
            }                                                                     \
        }                                                                         \
        CP_COMMIT();                                                              \
    } while (0)

    float acc[4][4][4];
#pragma unroll
    for (int i = 0; i < 4; i++)
#pragma unroll
        for (int j = 0; j < 4; j++)
#pragma unroll
            for (int k = 0; k < 4; k++) acc[i][j][k] = 0.0f;

    PREFETCH(0, 0);
    PREFETCH(1, 32);

    int tile = lane >> 3, trow = lane & 7;

    for (int kt = 0; kt < 16; kt++) {
        if (kt == 15) CP_WAIT0(); else CP_WAIT1();
        __syncthreads();
        uint32_t base = sb + (kt & 1) * STAGE_B;

#pragma unroll
        for (int ks = 0; ks < 2; ks++) {
            uint32_t ahi[4][4], alo[4][4];
#pragma unroll
            for (int mf = 0; mf < 4; mf++) {
                int row = wm * 64 + mf * 16 + (tile & 1) * 8 + trow;
                int col = ks * 16 + (tile >> 1) * 8;
                ldm_x4(ahi[mf], base + 0 * MAT_B + row * TSTRIDE + col * 2);
                ldm_x4(alo[mf], base + 1 * MAT_B + row * TSTRIDE + col * 2);
            }
            uint32_t bhi[4][2], blo[4][2];
#pragma unroll
            for (int p = 0; p < 2; p++) {
                int rn = wn * 32 + p * 16 + (tile >> 1) * 8 + trow;
                int ck = ks * 16 + (tile & 1) * 8;
                uint32_t r4[4];
                ldm_x4(r4, base + 2 * MAT_B + rn * TSTRIDE + ck * 2);
                bhi[2*p][0] = r4[0]; bhi[2*p][1] = r4[1];
                bhi[2*p+1][0] = r4[2]; bhi[2*p+1][1] = r4[3];
                ldm_x4(r4, base + 3 * MAT_B + rn * TSTRIDE + ck * 2);
                blo[2*p][0] = r4[0]; blo[2*p][1] = r4[1];
                blo[2*p+1][0] = r4[2]; blo[2*p+1][1] = r4[3];
            }
#pragma unroll
            for (int mf = 0; mf < 4; mf++)
#pragma unroll
                for (int nf = 0; nf < 4; nf++) {
                    mma_bf16(acc[mf][nf], ahi[mf], bhi[nf]);
                    mma_bf16(acc[mf][nf], ahi[mf], blo[nf]);
                    mma_bf16(acc[mf][nf], alo[mf], bhi[nf]);
                }
        }
        __syncthreads();
        if (kt < 14) PREFETCH(kt & 1, (kt + 2) * 32);
    }

    // epilogue with bias
#pragma unroll
    for (int mf = 0; mf < 4; mf++) {
        int r0 = row0 + wm * 64 + mf * 16 + (lane >> 2);
#pragma unroll
        for (int nf = 0; nf < 4; nf++) {
            int cb = col0 + wn * 32 + nf * 8 + 2 * (lane & 3);
            float b0v = __ldg(&bih[cb])     + __ldg(&bhh[cb]);
            float b1v = __ldg(&bih[cb + 1]) + __ldg(&bhh[cb + 1]);
            *(float2*)&g_xg[(size_t)r0 * Gdim + cb] =
                make_float2(acc[mf][nf][0] + b0v, acc[mf][nf][1] + b1v);
            *(float2*)&g_xg[(size_t)(r0 + 8) * Gdim + cb] =
                make_float2(acc[mf][nf][2] + b0v, acc[mf][nf][3] + b1v);
        }
    }
#undef PREFETCH
}

// ---------------- persistent recurrence (R1 version; h1 stored split) ----------------
__global__ __launch_bounds__(THR_REC, 1) void lstm_recur_kernel(
    const float* __restrict__ Whh, float* __restrict__ hseq,
    int out_bsh, float* __restrict__ hTo, float* __restrict__ cTo)
{
    extern __shared__ float sm[];
    float* Wsm = sm;                 // [16][512]
    float* hsm = sm + 16 * Hdim;     // [32][516]

    int tid = threadIdx.x;
    int b  = tid & 31;
    int jj = tid >> 5;
    int j0 = blockIdx.x * 4;

    for (int idx = tid; idx < 16 * 128; idx += THR_REC) {
        int r = idx >> 7, kq = (idx & 127) * 4;
        int q = r >> 2, j = r & 3;
        float4 v = *(const float4*)(Whh + (size_t)(q * Hdim + j0 + j) * Hdim + kq);
        *(float4*)&Wsm[r * Hdim + kq] = v;
    }
    g_hbuf[0][b * Hdim + j0 + jj] = 0.0f;
    float c = 0.0f;
    grid_barrier();

    const float*  xg_t = g_xg + (size_t)b * Gdim + (j0 + jj);
    const float4* wi4  = (const float4*)&Wsm[(0 * 4 + jj) * Hdim];
    const float4* wf4  = (const float4*)&Wsm[(1 * 4 + jj) * Hdim];
    const float4* wg4  = (const float4*)&Wsm[(2 * 4 + jj) * Hdim];
    const float4* wo4  = (const float4*)&Wsm[(3 * 4 + jj) * Hdim];
    const float4* hrow = (const float4*)&hsm[b * 516];

    for (int t = 0; t < Sdim; t++) {
        int cur = t & 1;
        float xi  = __ldg(xg_t + 0 * Hdim);
        float xf  = __ldg(xg_t + 1 * Hdim);
        float xgg = __ldg(xg_t + 2 * Hdim);
        float xo  = __ldg(xg_t + 3 * Hdim);

        const float4* src = (const float4*)g_hbuf[cur];
#pragma unroll
        for (int i = 0; i < 32; i++) {
            int idx = tid + i * THR_REC;
            float4 v = __ldcg(src + idx);
            int bb = idx >> 7, kq = idx & 127;
            *(float4*)&hsm[bb * 516 + kq * 4] = v;
        }
        __syncthreads();

        float ai = 0.f, af = 0.f, ag = 0.f, ao = 0.f;
#pragma unroll 4
        for (int kq = 0; kq < 128; kq++) {
            float4 h4 = hrow[kq];
            float4 w;
            w = wi4[kq]; ai += w.x*h4.x + w.y*h4.y + w.z*h4.z + w.w*h4.w;
            w = wf4[kq]; af += w.x*h4.x + w.y*h4.y + w.z*h4.z + w.w*h4.w;
            w = wg4[kq]; ag += w.x*h4.x + w.y*h4.y + w.z*h4.z + w.w*h4.w;
            w = wo4[kq]; ao += w.x*h4.x + w.y*h4.y + w.z*h4.z + w.w*h4.w;
        }
        ai += xi; af += xf; ag += xgg; ao += xo;

        float ig = 1.0f / (1.0f + __expf(-ai));
        float fg = 1.0f / (1.0f + __expf(-af));
        float gg = tanhf(ag);
        float og = 1.0f / (1.0f + __expf(-ao));
        c = fg * c + ig * gg;
        float h = og * tanhf(c);

        g_hbuf[cur ^ 1][b * Hdim + j0 + jj] = h;
        if (out_bsh) {
            hseq[((size_t)b * Sdim + t) * Hdim + j0 + jj] = h;
        } else {
            size_t r = ((size_t)t * Bdim + b) * Hdim + j0 + jj;
            __nv_bfloat16 hi = __float2bfloat16_rn(h);
            g_h1hi[r] = hi;
            g_h1lo[r] = __float2bfloat16_rn(h - __bfloat162float(hi));
        }
        if (hTo && t == Sdim - 1) {
            hTo[b * Hdim + j0 + jj] = h;
            cTo[b * Hdim + j0 + jj] = c;
        }
        xg_t += (size_t)Bdim * Gdim;
        grid_barrier();
    }
}

// ---------------- launch ----------------
extern "C" void kernel_launch(void* const* d_in, const int* in_sizes, int n_in,
                              void* d_out, int out_size) {
    (void)in_sizes; (void)n_in;
    const float* X   = (const float*)d_in[0];
    const float* Wih = (const float*)d_in[1];
    const float* Whh = (const float*)d_in[2];
    const float* bih = (const float*)d_in[3];
    const float* bhh = (const float*)d_in[4];
    float* out = (float*)d_out;

    size_t ht_elems = (size_t)Bdim * Sdim * Hdim;
    float* hTo = nullptr; float* cTo = nullptr;
    if ((size_t)out_size >= ht_elems + 2 * (size_t)Bdim * Hdim) {
        hTo = out + ht_elems;
        cTo = hTo + (size_t)Bdim * Hdim;
    }

    const int smem_rec  = (16 * Hdim + 32 * 516) * 4;   // 98816
    const int smem_gemm = 2 * STAGE_B;                  // 81920
    cudaFuncSetAttribute(lstm_recur_kernel,
                         cudaFuncAttributeMaxDynamicSharedMemorySize, smem_rec);
    cudaFuncSetAttribute(gemm_mma_kernel,
                         cudaFuncAttributeMaxDynamicSharedMemorySize, smem_gemm);

    conv_w_kernel<<<2048, 256>>>(Wih);
    conv_x_kernel<<<32768, 256>>>(X);

    dim3 ggrid(Gdim / 128, (Sdim * Bdim) / 128);   // (16, 512)

    // Layer 0
    gemm_mma_kernel<<<ggrid, 256, smem_gemm>>>(0, 0, bih, bhh);
    lstm_recur_kernel<<<NCTA_REC, THR_REC, smem_rec>>>(Whh, nullptr, 0, nullptr, nullptr);
    // Layer 1
    gemm_mma_kernel<<<ggrid, 256, smem_gemm>>>(1, 1, bih + Gdim, bhh + Gdim);
    lstm_recur_kernel<<<NCTA_REC, THR_REC, smem_rec>>>(Whh + (size_t)Gdim * Hdim,
                                                       out, 1, hTo, cTo);
}

// round 6
// speedup vs baseline: 1.5832x; 1.2679x over previous
#include <cuda_runtime.h>
#include <cuda_bf16.h>
#include <cstdint>

#define Sdim 2048
#define Bdim 32
#define Hdim 512
#define Gdim 2048   // 4*H
#define NCTA_REC 128

typedef unsigned long long ull;

// ---------------- scratch (module-load allocated) ----------------
__device__ float g_xg [(size_t)Sdim * Bdim * Gdim];               // [s*B+b][4H]
__device__ __align__(16) __nv_bfloat16 g_Ahi [(size_t)Sdim * Bdim * Hdim];
__device__ __align__(16) __nv_bfloat16 g_Alo [(size_t)Sdim * Bdim * Hdim];
__device__ __align__(16) __nv_bfloat16 g_h1hi[(size_t)Sdim * Bdim * Hdim];
__device__ __align__(16) __nv_bfloat16 g_h1lo[(size_t)Sdim * Bdim * Hdim];
__device__ __align__(16) __nv_bfloat16 g_Whi [2 * (size_t)Gdim * Hdim];
__device__ __align__(16) __nv_bfloat16 g_Wlo [2 * (size_t)Gdim * Hdim];
__device__ __align__(16) __nv_bfloat16 g_hb_hi[2][Bdim * Hdim];   // ping-pong h split
__device__ __align__(16) __nv_bfloat16 g_hb_lo[2][Bdim * Hdim];
__device__ unsigned g_cnt;
__device__ unsigned g_gen;

// ---------------- PTX helpers ----------------
__device__ __forceinline__ uint32_t smem_u32(const void* p) {
    uint32_t a;
    asm("{ .reg .u64 t; cvta.to.shared.u64 t, %1; cvt.u32.u64 %0, t; }" : "=r"(a) : "l"(p));
    return a;
}
#define CP_ASYNC16(dst, src) \
    asm volatile("cp.async.cg.shared.global [%0], [%1], 16;" :: "r"(dst), "l"(src))
#define CP_COMMIT() asm volatile("cp.async.commit_group;" ::: "memory")
#define CP_WAIT1()  asm volatile("cp.async.wait_group 1;" ::: "memory")
#define CP_WAIT0()  asm volatile("cp.async.wait_group 0;" ::: "memory")

__device__ __forceinline__ void ldm_x4(uint32_t* r, uint32_t addr) {
    asm volatile("ldmatrix.sync.aligned.m8n8.x4.shared.b16 {%0,%1,%2,%3}, [%4];"
                 : "=r"(r[0]), "=r"(r[1]), "=r"(r[2]), "=r"(r[3]) : "r"(addr));
}
__device__ __forceinline__ void mma_bf16(float* d, const uint32_t* a, const uint32_t* b) {
    asm volatile(
        "mma.sync.aligned.m16n8k16.row.col.f32.bf16.bf16.f32 "
        "{%0,%1,%2,%3}, {%4,%5,%6,%7}, {%8,%9}, {%0,%1,%2,%3};"
        : "+f"(d[0]), "+f"(d[1]), "+f"(d[2]), "+f"(d[3])
        : "r"(a[0]), "r"(a[1]), "r"(a[2]), "r"(a[3]), "r"(b[0]), "r"(b[1]));
}

// ---------------- grid barrier (validated R1/R2/R4; replay-safe) ----------------
__device__ __forceinline__ void grid_barrier() {
    __syncthreads();
    if (threadIdx.x == 0) {
        __threadfence();
        unsigned gen = *(volatile unsigned*)&g_gen;
        unsigned old = atomicAdd(&g_cnt, 1u);
        if (old == gridDim.x - 1) {
            atomicExch(&g_cnt, 0u);
            __threadfence();
            atomicAdd(&g_gen, 1u);
        } else {
            while (*(volatile unsigned*)&g_gen == gen) { __nanosleep(32); }
        }
        __threadfence();
    }
    __syncthreads();
}

// ---------------- fp32 -> bf16 hi/lo split ----------------
__device__ __forceinline__ void split4(float4 v, ull& hi, ull& lo) {
    union { __nv_bfloat16 h[4]; ull u; } H, L;
    float f[4] = {v.x, v.y, v.z, v.w};
#pragma unroll
    for (int i = 0; i < 4; i++) {
        __nv_bfloat16 a = __float2bfloat16_rn(f[i]);
        H.h[i] = a;
        L.h[i] = __float2bfloat16_rn(f[i] - __bfloat162float(a));
    }
    hi = H.u; lo = L.u;
}

// X[b][s][k] -> g_Ahi/g_Alo[(s*B+b)][k]
__global__ __launch_bounds__(256) void conv_x_kernel(const float* __restrict__ X) {
    size_t i = (size_t)blockIdx.x * 256 + threadIdx.x;
    int row = (int)(i >> 7);
    int c4  = (int)(i & 127);
    int b = row & 31, s = row >> 5;
    float4 v = __ldg((const float4*)(X + ((size_t)b * Sdim + s) * Hdim + c4 * 4));
    ull hi, lo;
    split4(v, hi, lo);
    *(ull*)(g_Ahi + (size_t)row * Hdim + c4 * 4) = hi;
    *(ull*)(g_Alo + (size_t)row * Hdim + c4 * 4) = lo;
}

// Wih[2][4H][H] -> g_Whi/g_Wlo
__global__ __launch_bounds__(256) void conv_w_kernel(const float* __restrict__ W) {
    size_t i = (size_t)blockIdx.x * 256 + threadIdx.x;
    float4 v = __ldg((const float4*)W + i);
    ull hi, lo;
    split4(v, hi, lo);
    *(ull*)(g_Whi + i * 4) = hi;
    *(ull*)(g_Wlo + i * 4) = lo;
}

// ---------------- mma.sync split-bf16 GEMM (validated R4) ----------------
#define TSTRIDE 80
#define MAT_B   (128 * TSTRIDE)
#define STAGE_B (4 * MAT_B)

__global__ __launch_bounds__(256, 1) void gemm_mma_kernel(
    int src_h1, int layer,
    const float* __restrict__ bih, const float* __restrict__ bhh)
{
    extern __shared__ char smem[];
    uint32_t sb = smem_u32(smem);
    int tid = threadIdx.x, wid = tid >> 5, lane = tid & 31;
    int col0 = blockIdx.x * 128;
    int row0 = blockIdx.y * 128;
    int wm = wid & 1, wn = wid >> 1;

    const __nv_bfloat16* a0p = (src_h1 ? g_h1hi : g_Ahi) + (size_t)row0 * Hdim;
    const __nv_bfloat16* a1p = (src_h1 ? g_h1lo : g_Alo) + (size_t)row0 * Hdim;
    const __nv_bfloat16* w0p = g_Whi + (size_t)layer * Gdim * Hdim + (size_t)col0 * Hdim;
    const __nv_bfloat16* w1p = g_Wlo + (size_t)layer * Gdim * Hdim + (size_t)col0 * Hdim;

    int ldr  = tid >> 2;
    int ldkc = tid & 3;

#define PREFETCH(stg, k0)                                                         \
    do {                                                                          \
        _Pragma("unroll")                                                         \
        for (int m = 0; m < 4; m++) {                                             \
            const __nv_bfloat16* mp = (m == 0 ? a0p : m == 1 ? a1p :              \
                                       m == 2 ? w0p : w1p);                       \
            _Pragma("unroll")                                                     \
            for (int i = 0; i < 2; i++) {                                         \
                int r = ldr + i * 64;                                             \
                uint32_t dst = sb + (stg) * STAGE_B + m * MAT_B +                 \
                               r * TSTRIDE + ldkc * 16;                           \
                const void* srcp = mp + (size_t)r * Hdim + (k0) + ldkc * 8;       \
                CP_ASYNC16(dst, srcp);                                            \
            }                                                                     \
        }                                                                         \
        CP_COMMIT();                                                              \
    } while (0)

    float acc[4][4][4];
#pragma unroll
    for (int i = 0; i < 4; i++)
#pragma unroll
        for (int j = 0; j < 4; j++)
#pragma unroll
            for (int k = 0; k < 4; k++) acc[i][j][k] = 0.0f;

    PREFETCH(0, 0);
    PREFETCH(1, 32);

    int tile = lane >> 3, trow = lane & 7;

    for (int kt = 0; kt < 16; kt++) {
        if (kt == 15) CP_WAIT0(); else CP_WAIT1();
        __syncthreads();
        uint32_t base = sb + (kt & 1) * STAGE_B;

#pragma unroll
        for (int ks = 0; ks < 2; ks++) {
            uint32_t ahi[4][4], alo[4][4];
#pragma unroll
            for (int mf = 0; mf < 4; mf++) {
                int row = wm * 64 + mf * 16 + (tile & 1) * 8 + trow;
                int col = ks * 16 + (tile >> 1) * 8;
                ldm_x4(ahi[mf], base + 0 * MAT_B + row * TSTRIDE + col * 2);
                ldm_x4(alo[mf], base + 1 * MAT_B + row * TSTRIDE + col * 2);
            }
            uint32_t bhi[4][2], blo[4][2];
#pragma unroll
            for (int p = 0; p < 2; p++) {
                int rn = wn * 32 + p * 16 + (tile >> 1) * 8 + trow;
                int ck = ks * 16 + (tile & 1) * 8;
                uint32_t r4[4];
                ldm_x4(r4, base + 2 * MAT_B + rn * TSTRIDE + ck * 2);
                bhi[2*p][0] = r4[0]; bhi[2*p][1] = r4[1];
                bhi[2*p+1][0] = r4[2]; bhi[2*p+1][1] = r4[3];
                ldm_x4(r4, base + 3 * MAT_B + rn * TSTRIDE + ck * 2);
                blo[2*p][0] = r4[0]; blo[2*p][1] = r4[1];
                blo[2*p+1][0] = r4[2]; blo[2*p+1][1] = r4[3];
            }
#pragma unroll
            for (int mf = 0; mf < 4; mf++)
#pragma unroll
                for (int nf = 0; nf < 4; nf++) {
                    mma_bf16(acc[mf][nf], ahi[mf], bhi[nf]);
                    mma_bf16(acc[mf][nf], ahi[mf], blo[nf]);
                    mma_bf16(acc[mf][nf], alo[mf], bhi[nf]);
                }
        }
        __syncthreads();
        if (kt < 14) PREFETCH(kt & 1, (kt + 2) * 32);
    }

#pragma unroll
    for (int mf = 0; mf < 4; mf++) {
        int r0 = row0 + wm * 64 + mf * 16 + (lane >> 2);
#pragma unroll
        for (int nf = 0; nf < 4; nf++) {
            int cb = col0 + wn * 32 + nf * 8 + 2 * (lane & 3);
            float b0v = __ldg(&bih[cb])     + __ldg(&bhh[cb]);
            float b1v = __ldg(&bih[cb + 1]) + __ldg(&bhh[cb + 1]);
            *(float2*)&g_xg[(size_t)r0 * Gdim + cb] =
                make_float2(acc[mf][nf][0] + b0v, acc[mf][nf][1] + b1v);
            *(float2*)&g_xg[(size_t)(r0 + 8) * Gdim + cb] =
                make_float2(acc[mf][nf][2] + b0v, acc[mf][nf][3] + b1v);
        }
    }
#undef PREFETCH
}

// ---------------- persistent recurrence on tensor cores (sync = grid_barrier) ----------------
#define RSTRIDE 1040   // bytes per smem bf16 row of 512 (+8 pad elems)
#define RED_OFF (96 * RSTRIDE)

__global__ __launch_bounds__(256, 1) void lstm_recur_mma(
    const float* __restrict__ Whh, float* __restrict__ hseq,
    int out_bsh, float* __restrict__ hTo, float* __restrict__ cTo)
{
    extern __shared__ char sm[];
    uint32_t sb = smem_u32(sm);
    uint32_t sWhi = sb;
    uint32_t sWlo = sb + 16 * RSTRIDE;
    uint32_t sHhi = sb + 32 * RSTRIDE;
    uint32_t sHlo = sb + 64 * RSTRIDE;
    float* red = (float*)(sm + RED_OFF);   // [8][32][18]

    int tid = threadIdx.x, wid = tid >> 5, lane = tid & 31;
    int b  = tid & 31;
    int jj = (tid >> 5) & 3;
    int j0 = blockIdx.x * 4;

    // stage Whh (split bf16) to smem: row r = q*4 + j  <-  Whh[q*512 + j0 + j]
    for (int idx = tid; idx < 2048; idx += 256) {
        int r = idx >> 7, c4 = idx & 127;
        int q = r >> 2, j = r & 3;
        float4 v = __ldg((const float4*)(Whh + (size_t)(q * Hdim + j0 + j) * Hdim + c4 * 4));
        ull hi, lo;
        split4(v, hi, lo);
        *(ull*)(sm + r * RSTRIDE + c4 * 8) = hi;
        *(ull*)(sm + 16 * RSTRIDE + r * RSTRIDE + c4 * 8) = lo;
    }
    if (tid < 128) {
        g_hb_hi[0][b * Hdim + j0 + jj] = __float2bfloat16(0.0f);
        g_hb_lo[0][b * Hdim + j0 + jj] = __float2bfloat16(0.0f);
    }
    __syncthreads();

    // preload B fragments: warp w owns k in [w*64, w*64+64)
    int kbase = wid * 64;
    int tile = lane >> 3, trow = lane & 7;
    uint32_t bhi[4][2][2], blo[4][2][2];
#pragma unroll
    for (int kt = 0; kt < 4; kt++) {
        int row = (tile >> 1) * 8 + trow;
        int col = kbase + kt * 16 + (tile & 1) * 8;
        uint32_t r4[4];
        ldm_x4(r4, sWhi + row * RSTRIDE + col * 2);
        bhi[kt][0][0] = r4[0]; bhi[kt][0][1] = r4[1];
        bhi[kt][1][0] = r4[2]; bhi[kt][1][1] = r4[3];
        ldm_x4(r4, sWlo + row * RSTRIDE + col * 2);
        blo[kt][0][0] = r4[0]; blo[kt][0][1] = r4[1];
        blo[kt][1][0] = r4[2]; blo[kt][1][1] = r4[3];
    }
    grid_barrier();   // h(0) visible everywhere

    float c_st = 0.0f;
    const float* xg_base = g_xg + (size_t)b * Gdim + (j0 + jj);

    for (int t = 0; t < Sdim; t++) {
        int cur = t & 1;
        float x_i = __ldg(xg_base + 0 * Hdim);
        float x_f = __ldg(xg_base + 1 * Hdim);
        float x_g = __ldg(xg_base + 2 * Hdim);
        float x_o = __ldg(xg_base + 3 * Hdim);

        // stage h(t-1) split: 2 x 32KB -> smem (barrier at loop end published it)
        const char* srchi = (const char*)g_hb_hi[cur];
        const char* srclo = (const char*)g_hb_lo[cur];
#pragma unroll
        for (int i = 0; i < 8; i++) {
            int idx = tid + i * 256;          // 0..2047 (16B chunks)
            int r = idx >> 6, ch = idx & 63;
            CP_ASYNC16(sHhi + r * RSTRIDE + ch * 16, srchi + idx * 16);
            CP_ASYNC16(sHlo + r * RSTRIDE + ch * 16, srclo + idx * 16);
        }
        CP_COMMIT();
        CP_WAIT0();
        __syncthreads();

        // MMA: [32 x 64-slice] x [64-slice x 16] partials
        float acc[2][2][4];
#pragma unroll
        for (int i = 0; i < 2; i++)
#pragma unroll
            for (int j = 0; j < 2; j++)
#pragma unroll
                for (int k = 0; k < 4; k++) acc[i][j][k] = 0.0f;

#pragma unroll
        for (int kt = 0; kt < 4; kt++) {
            int colb = kbase + kt * 16 + (tile >> 1) * 8;
            uint32_t ahi[2][4], alo[2][4];
#pragma unroll
            for (int mf = 0; mf < 2; mf++) {
                int row = mf * 16 + (tile & 1) * 8 + trow;
                ldm_x4(ahi[mf], sHhi + row * RSTRIDE + colb * 2);
                ldm_x4(alo[mf], sHlo + row * RSTRIDE + colb * 2);
            }
#pragma unroll
            for (int mf = 0; mf < 2; mf++)
#pragma unroll
                for (int nf = 0; nf < 2; nf++) {
                    mma_bf16(acc[mf][nf], ahi[mf], bhi[kt][nf]);
                    mma_bf16(acc[mf][nf], ahi[mf], blo[kt][nf]);
                    mma_bf16(acc[mf][nf], alo[mf], bhi[kt][nf]);
                }
        }

        // write per-warp partials to red[wid][m 0..31][n 0..15]
#pragma unroll
        for (int mf = 0; mf < 2; mf++)
#pragma unroll
            for (int nf = 0; nf < 2; nf++) {
                int row = mf * 16 + (lane >> 2);
                int col = nf * 8 + (lane & 3) * 2;
                float* p0 = red + ((wid * 32 + row) * 18 + col);
                p0[0] = acc[mf][nf][0]; p0[1] = acc[mf][nf][1];
                float* p1 = red + ((wid * 32 + row + 8) * 18 + col);
                p1[0] = acc[mf][nf][2]; p1[1] = acc[mf][nf][3];
            }
        __syncthreads();

        if (tid < 128) {
            float di = x_i, df = x_f, dg = x_g, do_ = x_o;
#pragma unroll
            for (int w = 0; w < 8; w++) {
                const float* rr = red + (w * 32 + b) * 18;
                di  += rr[0 * 4 + jj];
                df  += rr[1 * 4 + jj];
                dg  += rr[2 * 4 + jj];
                do_ += rr[3 * 4 + jj];
            }
            float ig = 1.0f / (1.0f + __expf(-di));
            float fg = 1.0f / (1.0f + __expf(-df));
            float gg = tanhf(dg);
            float og = 1.0f / (1.0f + __expf(-do_));
            c_st = fg * c_st + ig * gg;
            float h = og * tanhf(c_st);

            __nv_bfloat16 hh = __float2bfloat16_rn(h);
            __nv_bfloat16 hl = __float2bfloat16_rn(h - __bfloat162float(hh));
            g_hb_hi[cur ^ 1][b * Hdim + j0 + jj] = hh;
            g_hb_lo[cur ^ 1][b * Hdim + j0 + jj] = hl;
            if (out_bsh) {
                hseq[((size_t)b * Sdim + t) * Hdim + j0 + jj] = h;
                if (hTo && t == Sdim - 1) {
                    hTo[b * Hdim + j0 + jj] = h;
                    cTo[b * Hdim + j0 + jj] = c_st;
                }
            } else {
                size_t r = ((size_t)t * Bdim + b) * Hdim + j0 + jj;
                g_h1hi[r] = hh;
                g_h1lo[r] = hl;
            }
        }
        grid_barrier();   // publishes h(t); also isolates red / sH reuse

        xg_base += (size_t)Bdim * Gdim;
    }
}

// ---------------- launch ----------------
extern "C" void kernel_launch(void* const* d_in, const int* in_sizes, int n_in,
                              void* d_out, int out_size) {
    (void)in_sizes; (void)n_in;
    const float* X   = (const float*)d_in[0];
    const float* Wih = (const float*)d_in[1];
    const float* Whh = (const float*)d_in[2];
    const float* bih = (const float*)d_in[3];
    const float* bhh = (const float*)d_in[4];
    float* out = (float*)d_out;

    size_t ht_elems = (size_t)Bdim * Sdim * Hdim;
    float* hTo = nullptr; float* cTo = nullptr;
    if ((size_t)out_size >= ht_elems + 2 * (size_t)Bdim * Hdim) {
        hTo = out + ht_elems;
        cTo = hTo + (size_t)Bdim * Hdim;
    }

    const int smem_rec  = RED_OFF + 8 * 32 * 18 * 4;    // 118272
    const int smem_gemm = 2 * STAGE_B;                  // 81920
    cudaFuncSetAttribute(lstm_recur_mma,
                         cudaFuncAttributeMaxDynamicSharedMemorySize, smem_rec);
    cudaFuncSetAttribute(gemm_mma_kernel,
                         cudaFuncAttributeMaxDynamicSharedMemorySize, smem_gemm);

    conv_w_kernel<<<2048, 256>>>(Wih);
    conv_x_kernel<<<32768, 256>>>(X);

    dim3 ggrid(Gdim / 128, (Sdim * Bdim) / 128);   // (16, 512)

    // Layer 0
    gemm_mma_kernel<<<ggrid, 256, smem_gemm>>>(0, 0, bih, bhh);
    lstm_recur_mma<<<NCTA_REC, 256, smem_rec>>>(Whh, nullptr, 0, nullptr, nullptr);
    // Layer 1
    gemm_mma_kernel<<<ggrid, 256, smem_gemm>>>(1, 1, bih + Gdim, bhh + Gdim);
    lstm_recur_mma<<<NCTA_REC, 256, smem_rec>>>(Whh + (size_t)Gdim * Hdim,
                                                out, 1, hTo, cTo);
}